// round 10
// baseline (speedup 1.0000x reference)
#include <cuda_runtime.h>
#include <cuda_fp16.h>
#include <cstdint>
#include <cstddef>

#define BB 256
#define TT 600
#define HID 512
#define NVOCAB 83

// d_out layout (floats): [0,21248) output probs ; [21248,152320) new_h ; [152320,305920) attn
#define OFF_NEWH 21248
#define OFF_ATTN 152320

// ---------------- scratch (no allocation allowed) ----------------
__device__ float g_ha[BB * HID];
__device__ float g_scores[BB * TT];
__device__ float g_ctx[BB * HID];
__device__ float g_indec[BB * 300];
__device__ float g_gi[BB * 1536];
__device__ float g_gh[BB * 1536];
__device__ float g_logits[BB * NVOCAB];
__device__ __half g_Wt[HID * HID];   // W_ep transposed + fp16: Wt[n][k]

// ---------------- helpers ----------------
__device__ __forceinline__ float tanh_fast(float x) {
    float e, r;
    asm("ex2.approx.f32 %0, %1;" : "=f"(e) : "f"(x * 2.8853900817779268f));
    asm("rcp.approx.f32 %0, %1;" : "=f"(r) : "f"(e + 1.0f));
    return 1.0f - 2.0f * r;
}

__device__ __forceinline__ void mma_fp16(float* c, const uint32_t* a, const uint32_t* b) {
    asm volatile(
        "mma.sync.aligned.m16n8k16.row.col.f32.f16.f16.f32 "
        "{%0,%1,%2,%3}, {%4,%5,%6,%7}, {%8,%9}, {%0,%1,%2,%3};\n"
        : "+f"(c[0]), "+f"(c[1]), "+f"(c[2]), "+f"(c[3])
        : "r"(a[0]), "r"(a[1]), "r"(a[2]), "r"(a[3]), "r"(b[0]), "r"(b[1]));
}

__device__ __forceinline__ void ldsm_x4(uint32_t& r0, uint32_t& r1, uint32_t& r2,
                                        uint32_t& r3, uint32_t addr) {
    asm volatile("ldmatrix.sync.aligned.m8n8.x4.shared.b16 {%0,%1,%2,%3}, [%4];"
                 : "=r"(r0), "=r"(r1), "=r"(r2), "=r"(r3) : "r"(addr));
}

#define CP_ASYNC16(dst, src) \
    asm volatile("cp.async.cg.shared.global [%0], [%1], 16;" :: "r"(dst), "l"(src))
#define CP_COMMIT() asm volatile("cp.async.commit_group;" ::: "memory")
#define CP_WAIT1()  asm volatile("cp.async.wait_group 1;" ::: "memory")
#define CP_WAIT0()  asm volatile("cp.async.wait_group 0;" ::: "memory")

__device__ __forceinline__ uint32_t smem_u32(const void* p) {
    uint32_t a;
    asm("{ .reg .u64 t; cvta.to.shared.u64 t, %1; cvt.u32.u64 %0, t; }" : "=r"(a) : "l"(p));
    return a;
}

// ---------------- fused scores kernel (fp16 mma + LDSM, 3-buf single-bar pipe) ----
// C[M=153600, N=512] = enc[M,512] @ W_ep[512,512]  (W pre-transposed fp16: Wt[n][k])
// scores[b][t] = b_v + sum_n w_v[n] * tanh(C[m][n] + ha[b][n] + b_ep[n]),  m = t*256 + b
// Block: 96 rows (grid 1600); A fp16 smem-resident; N in 2 chunks of 256;
// warp tile 48x64 (2 M-warps x 4 N-warps); W in 16 global K=64 slabs, 3-buffer
// cp.async pipeline with ONE barrier per slab.
#define A_STRIDE_B 1040                              // bytes per A row (520 halfs)
#define A_SM_BYTES (96 * A_STRIDE_B)                 // 99840
#define W_ROW_B 144                                  // 64 k halfs (128 B) + 16 B pad
#define W_SLAB_B (256 * W_ROW_B)                     // 36864
#define DYN_SMEM_SCORES (A_SM_BYTES + 3 * W_SLAB_B)  // 210432

__global__ void __launch_bounds__(256, 1)
scores_fp16(const float* __restrict__ enc, const __half* __restrict__ Wt,
            const float* __restrict__ bep, const float* __restrict__ ha,
            const float* __restrict__ wv, const float* __restrict__ bv,
            float* __restrict__ scores) {
    extern __shared__ unsigned char dsm[];
    uint32_t* A32 = reinterpret_cast<uint32_t*>(dsm);
    __shared__ float wv_sm[512];
    __shared__ float bep_sm[512];
    __shared__ float stage_sm[384];

    const int tid = threadIdx.x;
    const int lane = tid & 31;
    const int w = tid >> 5;
    const int wm = w >> 2;        // 0..1  (M half: 48 rows)
    const int wn = w & 3;         // 0..3  (N quarter: 64 cols)
    const int g = lane >> 2;      // 0..7
    const int t4 = lane & 3;      // 0..3
    const int m0 = blockIdx.x * 96;

    const uint32_t asm_base = smem_u32(dsm);
    const uint32_t wsm_base = asm_base + A_SM_BYTES;

    // issue one K=64 W slab: global slab sg (nc = sg>>3, s = sg&7), buffer sg%3
    auto issueW = [&](int sg) {
        const int nc = sg >> 3, s = sg & 7;
        const uint32_t bbase = wsm_base + (uint32_t)(sg % 3) * W_SLAB_B;
#pragma unroll
        for (int i = 0; i < 8; i++) {
            int idx = tid + i * 256;              // 0..2047 (256 rows x 8 x 16B)
            int n = idx >> 3, c8 = idx & 7;
            uint32_t dst = bbase + n * W_ROW_B + c8 * 16;
            const __half* src = Wt + (size_t)(nc * 256 + n) * 512 + s * 64 + c8 * 8;
            CP_ASYNC16(dst, src);
        }
        CP_COMMIT();
    };

    issueW(0);
    issueW(1);

    for (int i = tid; i < 512; i += 256) { wv_sm[i] = wv[i]; bep_sm[i] = bep[i]; }

    // Load A panel (96 x 512), convert fp32 -> fp16 pairs, smem-resident
#pragma unroll 8
    for (int i = 0; i < 48; i++) {
        int idx = tid + i * 256;                  // 0..12287 (128 float4 per row)
        int r = idx >> 7, c4 = idx & 127;
        float4 v = *reinterpret_cast<const float4*>(enc + (size_t)(m0 + r) * 512 + (c4 << 2));
        __half2 h0 = __floats2half2_rn(v.x, v.y);
        __half2 h1 = __floats2half2_rn(v.z, v.w);
        uint32_t* d = A32 + r * (A_STRIDE_B / 4) + c4 * 2;
        d[0] = *reinterpret_cast<uint32_t*>(&h0);
        d[1] = *reinterpret_cast<uint32_t*>(&h1);
    }
    __syncthreads();

    // ---- per-thread LDSM base addresses ----
    uint32_t a_addr[3];
    {
        int ar = wm * 48 + (lane & 15);
        int ak = (lane >> 4) * 16;
#pragma unroll
        for (int mt = 0; mt < 3; mt++)
            a_addr[mt] = asm_base + (uint32_t)((ar + mt * 16) * A_STRIDE_B + ak);
    }
    uint32_t b_addr[3][4];
    {
        int br = wn * 64 + (lane & 7) + ((lane >> 4) & 1) * 8;
        int bk = ((lane >> 3) & 1) * 16;
#pragma unroll
        for (int buf = 0; buf < 3; buf++)
#pragma unroll
            for (int ntp = 0; ntp < 4; ntp++)
                b_addr[buf][ntp] = wsm_base + (uint32_t)buf * W_SLAB_B +
                                   (uint32_t)((br + ntp * 16) * W_ROW_B + bk);
    }

    float spart[6];
#pragma unroll
    for (int i = 0; i < 6; i++) spart[i] = 0.f;

    float acc[3][8][4];
#pragma unroll
    for (int mt = 0; mt < 3; mt++)
#pragma unroll
        for (int nt = 0; nt < 8; nt++)
#pragma unroll
            for (int q = 0; q < 4; q++) acc[mt][nt][q] = 0.f;

    for (int sg = 0; sg < 16; sg++) {
        if (sg < 15) { CP_WAIT1(); } else { CP_WAIT0(); }
        __syncthreads();
        if (sg < 14) issueW(sg + 2);     // fills buffer (sg+2)%3 == (sg-1)%3: safe past bar
        const int buf = sg % 3;
        const uint32_t akbase = (uint32_t)((sg & 7) * 128);
#pragma unroll
        for (int ks = 0; ks < 4; ks++) {
            const uint32_t akb = akbase + ks * 32;
            uint32_t afr[3][4];
#pragma unroll
            for (int mt = 0; mt < 3; mt++)
                ldsm_x4(afr[mt][0], afr[mt][1], afr[mt][2], afr[mt][3],
                        a_addr[mt] + akb);
#pragma unroll
            for (int ntp = 0; ntp < 4; ntp++) {
                uint32_t b0, b1, b2, b3;
                ldsm_x4(b0, b1, b2, b3, b_addr[buf][ntp] + (uint32_t)(ks * 32));
                uint32_t be[2] = { b0, b1 };
                uint32_t bo[2] = { b2, b3 };
#pragma unroll
                for (int mt = 0; mt < 3; mt++) {
                    mma_fp16(acc[mt][ntp * 2 + 0], afr[mt], be);
                    mma_fp16(acc[mt][ntp * 2 + 1], afr[mt], bo);
                }
            }
        }

        if ((sg & 7) == 7) {
            // chunk boundary: fused epilogue (overlaps in-flight W cp.async)
            const int nc = sg >> 3;
#pragma unroll
            for (int mt = 0; mt < 3; mt++) {
#pragma unroll
                for (int qr = 0; qr < 2; qr++) {
                    const int rowl = wm * 48 + mt * 16 + qr * 8 + g;
                    const int brow = (m0 + rowl) & 255;
                    const float* harow = ha + (size_t)brow * 512;
                    float acc_s = 0.f;
#pragma unroll
                    for (int nt = 0; nt < 8; nt++) {
                        const int col0 = nc * 256 + wn * 64 + nt * 8 + 2 * t4;
                        float2 hv = *reinterpret_cast<const float2*>(harow + col0);
                        float v0 = acc[mt][nt][qr * 2 + 0] + hv.x + bep_sm[col0];
                        float v1 = acc[mt][nt][qr * 2 + 1] + hv.y + bep_sm[col0 + 1];
                        acc_s += wv_sm[col0] * tanh_fast(v0);
                        acc_s += wv_sm[col0 + 1] * tanh_fast(v1);
                    }
                    spart[mt * 2 + qr] += acc_s;
                }
            }
            if (nc == 0) {
#pragma unroll
                for (int mt = 0; mt < 3; mt++)
#pragma unroll
                    for (int nt = 0; nt < 8; nt++)
#pragma unroll
                        for (int q = 0; q < 4; q++) acc[mt][nt][q] = 0.f;
            }
        }
    }

    // deterministic reduction: quad (t4) via shfl, then across the 4 N-warps via smem
#pragma unroll
    for (int i = 0; i < 6; i++) {
        spart[i] += __shfl_xor_sync(0xffffffffu, spart[i], 1);
        spart[i] += __shfl_xor_sync(0xffffffffu, spart[i], 2);
    }
    __syncthreads();
    if (t4 == 0) {
#pragma unroll
        for (int i = 0; i < 6; i++) {
            int rowl = wm * 48 + (i >> 1) * 16 + (i & 1) * 8 + g;
            stage_sm[wn * 96 + rowl] = spart[i];
        }
    }
    __syncthreads();
    if (tid < 96) {
        float s = stage_sm[tid] + stage_sm[96 + tid] + stage_sm[192 + tid] +
                  stage_sm[288 + tid] + bv[0];
        int m = m0 + tid;
        scores[(size_t)(m & 255) * TT + (m >> 8)] = s;
    }
}

// ---------------- W_ep transpose+convert: Wt[n][k] = fp16(W[k][n]) ----------------
__global__ void transpose_h(const float* __restrict__ src, __half* __restrict__ dst) {
    __shared__ float t[32][33];
    const int tx = threadIdx.x, ty = threadIdx.y;
    const int kx = blockIdx.y * 32;
    const int nx = blockIdx.x * 32;
#pragma unroll
    for (int i = ty; i < 32; i += 8)
        t[i][tx] = src[(size_t)(kx + i) * 512 + nx + tx];
    __syncthreads();
#pragma unroll
    for (int i = ty; i < 32; i += 8)
        dst[(size_t)(nx + i) * 512 + kx + tx] = __float2half_rn(t[tx][i]);
}

// ---------------- generic tiled fp32 SGEMM + bias ----------------
__global__ void __launch_bounds__(256)
sgemm_bias(const float* __restrict__ A, const float* __restrict__ B,
           const float* __restrict__ bias, float* __restrict__ C,
           int N, int K, int ldc) {
    __shared__ float As[16][68];
    __shared__ float Bs[16][68];
    const int tid = threadIdx.x;
    const int tx = tid & 15, ty = tid >> 4;
    const int m0 = blockIdx.y * 64, n0 = blockIdx.x * 64;
    float acc[4][4] = {};

    for (int k0 = 0; k0 < K; k0 += 16) {
#pragma unroll
        for (int i = 0; i < 4; i++) {
            int idx = tid + i * 256;
            int r = idx >> 4, kc = idx & 15;
            float v = 0.f;
            if (k0 + kc < K) v = A[(size_t)(m0 + r) * K + k0 + kc];
            As[kc][r] = v;
        }
#pragma unroll
        for (int i = 0; i < 4; i++) {
            int idx = tid + i * 256;
            int kr = idx >> 6, c = idx & 63;
            float v = 0.f;
            if (k0 + kr < K && n0 + c < N) v = B[(size_t)(k0 + kr) * N + n0 + c];
            Bs[kr][c] = v;
        }
        __syncthreads();
#pragma unroll
        for (int kc = 0; kc < 16; kc++) {
            float a[4], bb[4];
#pragma unroll
            for (int i = 0; i < 4; i++) a[i] = As[kc][ty * 4 + i];
#pragma unroll
            for (int j = 0; j < 4; j++) bb[j] = Bs[kc][tx * 4 + j];
#pragma unroll
            for (int i = 0; i < 4; i++)
#pragma unroll
                for (int j = 0; j < 4; j++) acc[i][j] += a[i] * bb[j];
        }
        __syncthreads();
    }
#pragma unroll
    for (int i = 0; i < 4; i++) {
#pragma unroll
        for (int j = 0; j < 4; j++) {
            int col = n0 + tx * 4 + j;
            if (col < N)
                C[(size_t)(m0 + ty * 4 + i) * ldc + col] = acc[i][j] + bias[col];
        }
    }
}

// ---------------- softmax over T=600 -> attn in d_out ----------------
__global__ void softmax_attn(const float* __restrict__ scores, float* __restrict__ attn) {
    __shared__ float red[256];
    const int b = blockIdx.x, tid = threadIdx.x;
    const float* s = scores + b * TT;
    float* o = attn + b * TT;

    float m = -1e30f;
    for (int t = tid; t < TT; t += 256) m = fmaxf(m, s[t]);
    red[tid] = m;
    __syncthreads();
    for (int st = 128; st > 0; st >>= 1) {
        if (tid < st) red[tid] = fmaxf(red[tid], red[tid + st]);
        __syncthreads();
    }
    m = red[0];
    __syncthreads();

    float sum = 0.f;
    for (int t = tid; t < TT; t += 256) {
        float e = expf(s[t] - m);
        o[t] = e;
        sum += e;
    }
    red[tid] = sum;
    __syncthreads();
    for (int st = 128; st > 0; st >>= 1) {
        if (tid < st) red[tid] += red[tid + st];
        __syncthreads();
    }
    float inv = 1.f / red[0];
    for (int t = tid; t < TT; t += 256) o[t] *= inv;
}

// ---------------- context[b][h] = sum_t attn[b][t] * enc[t][b][h] ----------------
__global__ void __launch_bounds__(128)
context_kernel(const float* __restrict__ enc, const float* __restrict__ attn,
               float* __restrict__ ctx) {
    __shared__ float a_sm[TT];
    const int b = blockIdx.y, hc = blockIdx.x;
    const int tid = threadIdx.x;
    for (int t = tid; t < TT; t += 128) a_sm[t] = attn[b * TT + t];
    __syncthreads();
    const int h = hc * 128 + tid;
    const float* base = enc + (size_t)b * 512 + h;
    float a0 = 0.f, a1 = 0.f, a2 = 0.f, a3 = 0.f;
    float a4 = 0.f, a5 = 0.f, a6 = 0.f, a7 = 0.f;
    for (int t = 0; t < TT; t += 8) {
        a0 += a_sm[t + 0] * base[(size_t)(t + 0) * 131072];
        a1 += a_sm[t + 1] * base[(size_t)(t + 1) * 131072];
        a2 += a_sm[t + 2] * base[(size_t)(t + 2) * 131072];
        a3 += a_sm[t + 3] * base[(size_t)(t + 3) * 131072];
        a4 += a_sm[t + 4] * base[(size_t)(t + 4) * 131072];
        a5 += a_sm[t + 5] * base[(size_t)(t + 5) * 131072];
        a6 += a_sm[t + 6] * base[(size_t)(t + 6) * 131072];
        a7 += a_sm[t + 7] * base[(size_t)(t + 7) * 131072];
    }
    ctx[b * 512 + h] = ((a0 + a1) + (a2 + a3)) + ((a4 + a5) + (a6 + a7));
}

// ---------------- argmax over vocab + embedding gather ----------------
__global__ void argmax_embed(const float* __restrict__ in_char, const float* __restrict__ emb,
                             float* __restrict__ indec) {
    const int b = threadIdx.x;
    const float* row = in_char + b * NVOCAB;
    float m = row[0];
    int idx = 0;
    for (int v = 1; v < NVOCAB; v++) {
        float x = row[v];
        if (x > m) { m = x; idx = v; }
    }
    const float* e = emb + idx * 50;
    float* o = indec + b * 300;
    for (int j = 0; j < 50; j++) o[j] = e[j];
}

// ---------------- GRU cell elementwise ----------------
__global__ void gru_kernel(const float* __restrict__ gi, const float* __restrict__ gh,
                           const float* __restrict__ h, float* __restrict__ newh) {
    const int idx = blockIdx.x * 256 + threadIdx.x;
    const int b = idx >> 9, n = idx & 511;
    const float* gib = gi + b * 1536;
    const float* ghb = gh + b * 1536;
    float ir = gib[n], iz = gib[512 + n], in_ = gib[1024 + n];
    float hr = ghb[n], hz = ghb[512 + n], hn = ghb[1024 + n];
    float r = 1.f / (1.f + expf(-(ir + hr)));
    float z = 1.f / (1.f + expf(-(iz + hz)));
    float nn = tanhf(in_ + r * hn);
    newh[idx] = (1.f - z) * nn + z * h[idx];
}

// ---------------- output softmax over vocab ----------------
__global__ void __launch_bounds__(128)
softmax_out(const float* __restrict__ logits, float* __restrict__ out) {
    __shared__ float red[128];
    const int b = blockIdx.x, tid = threadIdx.x;
    float v = (tid < NVOCAB) ? logits[b * NVOCAB + tid] : -1e30f;
    red[tid] = v;
    __syncthreads();
    for (int st = 64; st > 0; st >>= 1) {
        if (tid < st) red[tid] = fmaxf(red[tid], red[tid + st]);
        __syncthreads();
    }
    float m = red[0];
    __syncthreads();
    float e = (tid < NVOCAB) ? expf(v - m) : 0.f;
    red[tid] = e;
    __syncthreads();
    for (int st = 64; st > 0; st >>= 1) {
        if (tid < st) red[tid] += red[tid + st];
        __syncthreads();
    }
    if (tid < NVOCAB) out[b * NVOCAB + tid] = e / red[0];
}

// ---------------- launch ----------------
extern "C" void kernel_launch(void* const* d_in, const int* in_sizes, int n_in,
                              void* d_out, int out_size) {
    const float* in_char = (const float*)d_in[0];
    const float* hidden  = (const float*)d_in[1];
    const float* enc     = (const float*)d_in[2];
    const float* W_hp = (const float*)d_in[3];
    const float* b_hp = (const float*)d_in[4];
    const float* W_ep = (const float*)d_in[5];
    const float* b_ep = (const float*)d_in[6];
    const float* w_v  = (const float*)d_in[7];
    const float* b_v  = (const float*)d_in[8];
    const float* W_cs = (const float*)d_in[9];
    const float* b_cs = (const float*)d_in[10];
    const float* emb  = (const float*)d_in[11];
    const float* W_ih = (const float*)d_in[12];
    const float* b_ih = (const float*)d_in[13];
    const float* W_hh = (const float*)d_in[14];
    const float* b_hh = (const float*)d_in[15];
    const float* W_out = (const float*)d_in[16];
    const float* b_out = (const float*)d_in[17];

    float* out = (float*)d_out;
    float* out_prob = out;
    float* out_newh = out + OFF_NEWH;
    float* out_attn = out + OFF_ATTN;

    float *ha, *scores, *ctx, *indec, *gi, *gh, *logits;
    __half* Wt;
    cudaGetSymbolAddress((void**)&ha, g_ha);
    cudaGetSymbolAddress((void**)&scores, g_scores);
    cudaGetSymbolAddress((void**)&ctx, g_ctx);
    cudaGetSymbolAddress((void**)&indec, g_indec);
    cudaGetSymbolAddress((void**)&gi, g_gi);
    cudaGetSymbolAddress((void**)&gh, g_gh);
    cudaGetSymbolAddress((void**)&logits, g_logits);
    cudaGetSymbolAddress((void**)&Wt, g_Wt);

    cudaFuncSetAttribute(scores_fp16, cudaFuncAttributeMaxDynamicSharedMemorySize,
                         DYN_SMEM_SCORES);

    // 0) transpose + fp16-convert W_ep -> Wt[n][k]
    transpose_h<<<dim3(16, 16), dim3(32, 8)>>>(W_ep, Wt);

    // 1) hidden_attn = hidden @ W_hp + b_hp  (256x512x512)
    sgemm_bias<<<dim3(8, 4), 256>>>(hidden, W_hp, b_hp, ha, 512, 512, 512);

    // 2) fused scores: fp16 mma GEMM (ldmatrix, 3-buf pipe) + tanh + w_v reduce
    scores_fp16<<<1600, 256, DYN_SMEM_SCORES>>>(enc, Wt, b_ep, ha, w_v, b_v, scores);

    // 3) attn = softmax(scores) -> d_out
    softmax_attn<<<256, 256>>>(scores, out_attn);

    // 4) context = einsum('bth,bt->bh')
    context_kernel<<<dim3(4, 256), 128>>>(enc, out_attn, ctx);

    // 5) argmax + embedding into in_dec[:, :50]
    argmax_embed<<<1, 256>>>(in_char, emb, indec);

    // 6) in_dec[:, 50:300] = context @ W_cs + b_cs
    sgemm_bias<<<dim3(4, 4), 256>>>(ctx, W_cs, b_cs, indec + 50, 250, 512, 300);

    // 7) gi = in_dec @ W_ih + b_ih
    sgemm_bias<<<dim3(24, 4), 256>>>(indec, W_ih, b_ih, gi, 1536, 300, 1536);

    // 8) gh = h @ W_hh + b_hh
    sgemm_bias<<<dim3(24, 4), 256>>>(hidden, W_hh, b_hh, gh, 1536, 512, 1536);

    // 9) GRU -> new_h in d_out
    gru_kernel<<<512, 256>>>(gi, gh, hidden, out_newh);

    // 10) logits = new_h @ W_out + b_out
    sgemm_bias<<<dim3(2, 4), 256>>>(out_newh, W_out, b_out, logits, NVOCAB, 512, NVOCAB);

    // 11) output = softmax(logits) -> d_out
    softmax_out<<<256, 128>>>(logits, out_prob);
}

// round 11
// speedup vs baseline: 1.2887x; 1.2887x over previous
#include <cuda_runtime.h>
#include <cuda_fp16.h>
#include <cstdint>
#include <cstddef>

#define BB 256
#define TT 600
#define HID 512
#define NVOCAB 83

// d_out layout (floats): [0,21248) output probs ; [21248,152320) new_h ; [152320,305920) attn
#define OFF_NEWH 21248
#define OFF_ATTN 152320

// ---------------- scratch (no allocation allowed) ----------------
__device__ float g_ha[BB * HID];
__device__ float g_scores[BB * TT];
__device__ float g_ctx[BB * HID];
__device__ float g_ctxp[4 * BB * HID];     // split-T partial sums
__device__ float g_indec[BB * 300];
__device__ float g_gi[BB * 1536];
__device__ float g_gh[BB * 1536];
__device__ __half g_Wt[HID * HID];         // W_ep transposed + fp16: Wt[n][k]

// ---------------- helpers ----------------
__device__ __forceinline__ float tanh_fast(float x) {
    float e, r;
    asm("ex2.approx.f32 %0, %1;" : "=f"(e) : "f"(x * 2.8853900817779268f));
    asm("rcp.approx.f32 %0, %1;" : "=f"(r) : "f"(e + 1.0f));
    return 1.0f - 2.0f * r;
}

__device__ __forceinline__ void mma_fp16(float* c, const uint32_t* a, const uint32_t* b) {
    asm volatile(
        "mma.sync.aligned.m16n8k16.row.col.f32.f16.f16.f32 "
        "{%0,%1,%2,%3}, {%4,%5,%6,%7}, {%8,%9}, {%0,%1,%2,%3};\n"
        : "+f"(c[0]), "+f"(c[1]), "+f"(c[2]), "+f"(c[3])
        : "r"(a[0]), "r"(a[1]), "r"(a[2]), "r"(a[3]), "r"(b[0]), "r"(b[1]));
}

__device__ __forceinline__ void ldsm_x4(uint32_t& r0, uint32_t& r1, uint32_t& r2,
                                        uint32_t& r3, uint32_t addr) {
    asm volatile("ldmatrix.sync.aligned.m8n8.x4.shared.b16 {%0,%1,%2,%3}, [%4];"
                 : "=r"(r0), "=r"(r1), "=r"(r2), "=r"(r3) : "r"(addr));
}

#define CP_ASYNC16(dst, src) \
    asm volatile("cp.async.cg.shared.global [%0], [%1], 16;" :: "r"(dst), "l"(src))
#define CP_COMMIT() asm volatile("cp.async.commit_group;" ::: "memory")
#define CP_WAIT1()  asm volatile("cp.async.wait_group 1;" ::: "memory")
#define CP_WAIT0()  asm volatile("cp.async.wait_group 0;" ::: "memory")

__device__ __forceinline__ uint32_t smem_u32(const void* p) {
    uint32_t a;
    asm("{ .reg .u64 t; cvta.to.shared.u64 t, %1; cvt.u32.u64 %0, t; }" : "=r"(a) : "l"(p));
    return a;
}

// ---------------- fused scores kernel (EXACT R8 best: fp16 mma + LDSM) ----------------
// C[M=153600, N=512] = enc[M,512] @ W_ep[512,512]  (W pre-transposed fp16: Wt[n][k])
// scores[b][t] = b_v + sum_n w_v[n] * tanh(C[m][n] + ha[b][n] + b_ep[n]),  m = t*256 + b
// Block: 128 rows, A fp16 smem-resident; N in 2 chunks of 256; warp tile 64x64;
// W streamed in 64-K slabs via cp.async double buffer; fragments via LDSM.
#define A_STRIDE_P 260                              // u32 pairs per A row (520 halfs, 1040 B)
#define A_SM_BYTES (128 * A_STRIDE_P * 4)           // 133120
#define W_STRIDE_P 36                               // u32 pairs per W row (144 B)
#define W_SLAB_U32 (256 * W_STRIDE_P)               // 9216 u32 = 36864 B
#define DYN_SMEM_SCORES (A_SM_BYTES + 2 * W_SLAB_U32 * 4)   // 206848

__global__ void __launch_bounds__(256, 1)
scores_fp16(const float* __restrict__ enc, const __half* __restrict__ Wt,
            const float* __restrict__ bep, const float* __restrict__ ha,
            const float* __restrict__ wv, const float* __restrict__ bv,
            float* __restrict__ scores) {
    extern __shared__ unsigned char dsm[];
    uint32_t* A32 = reinterpret_cast<uint32_t*>(dsm);
    __shared__ float wv_sm[512];
    __shared__ float bep_sm[512];
    __shared__ float stage_sm[512];

    const int tid = threadIdx.x;
    const int lane = tid & 31;
    const int w = tid >> 5;
    const int wm = w >> 2;        // 0..1  (M half: 64 rows)
    const int wn = w & 3;         // 0..3  (N quarter: 64 cols)
    const int g = lane >> 2;      // 0..7
    const int t4 = lane & 3;      // 0..3
    const int m0 = blockIdx.x * 128;

    const uint32_t wsm_base = smem_u32(dsm + A_SM_BYTES);
    const uint32_t asm_base = smem_u32(dsm);
    uint32_t* W32 = reinterpret_cast<uint32_t*>(dsm + A_SM_BYTES);
    (void)W32;

    // issue W slab: nc chunk, slab s (64 K), buffer buf
    auto issueW = [&](int nc, int s, int buf) {
#pragma unroll
        for (int i = 0; i < 8; i++) {
            int idx = tid + i * 256;              // 0..2047
            int n = idx >> 3, c8 = idx & 7;       // 256 rows x 8 chunks of 16B
            uint32_t dst = wsm_base + (uint32_t)buf * (W_SLAB_U32 * 4) + n * 144 + c8 * 16;
            const __half* src = Wt + (size_t)(nc * 256 + n) * 512 + s * 64 + c8 * 8;
            CP_ASYNC16(dst, src);
        }
        CP_COMMIT();
    };

    // prefetch first two W slabs of chunk 0 (overlaps A load below)
    issueW(0, 0, 0);
    issueW(0, 1, 1);

    for (int i = tid; i < 512; i += 256) { wv_sm[i] = wv[i]; bep_sm[i] = bep[i]; }

    // Load A panel (128 x 512), convert fp32 -> fp16 pairs, smem-resident
#pragma unroll 8
    for (int i = 0; i < 64; i++) {
        int idx = tid + i * 256;                  // 0..16383 (128 float4 per row)
        int r = idx >> 7, c4 = idx & 127;
        float4 v = *reinterpret_cast<const float4*>(enc + (size_t)(m0 + r) * 512 + (c4 << 2));
        __half2 h0 = __floats2half2_rn(v.x, v.y);
        __half2 h1 = __floats2half2_rn(v.z, v.w);
        uint32_t* d = A32 + r * A_STRIDE_P + c4 * 2;
        d[0] = *reinterpret_cast<uint32_t*>(&h0);
        d[1] = *reinterpret_cast<uint32_t*>(&h1);
    }
    __syncthreads();

    // ---- per-thread LDSM base addresses ----
    uint32_t a_addr[4];
    {
        int ar = wm * 64 + (lane & 15);
        int ak = (lane >> 4) * 16;
#pragma unroll
        for (int mt = 0; mt < 4; mt++)
            a_addr[mt] = asm_base + (uint32_t)((ar + mt * 16) * 1040 + ak);
    }
    uint32_t b_addr[2][4];
    {
        int br = wn * 64 + (lane & 7) + ((lane >> 4) & 1) * 8;
        int bk = ((lane >> 3) & 1) * 16;
#pragma unroll
        for (int buf = 0; buf < 2; buf++)
#pragma unroll
            for (int ntp = 0; ntp < 4; ntp++)
                b_addr[buf][ntp] = wsm_base + (uint32_t)buf * (W_SLAB_U32 * 4) +
                                   (uint32_t)((br + ntp * 16) * 144 + bk);
    }

    float spart[8];
#pragma unroll
    for (int i = 0; i < 8; i++) spart[i] = 0.f;

    for (int nc = 0; nc < 2; nc++) {
        float acc[4][8][4];
#pragma unroll
        for (int mt = 0; mt < 4; mt++)
#pragma unroll
            for (int nt = 0; nt < 8; nt++)
#pragma unroll
                for (int q = 0; q < 4; q++) acc[mt][nt][q] = 0.f;

        for (int s = 0; s < 8; s++) {
            if (s < 7) { CP_WAIT1(); } else { CP_WAIT0(); }
            __syncthreads();
            const int buf = s & 1;
            const uint32_t koff = (uint32_t)(s * 128);
#pragma unroll
            for (int ks = 0; ks < 4; ks++) {
                const uint32_t kb = koff + ks * 32;
                uint32_t afr[4][4];
#pragma unroll
                for (int mt = 0; mt < 4; mt++)
                    ldsm_x4(afr[mt][0], afr[mt][1], afr[mt][2], afr[mt][3],
                            a_addr[mt] + kb);
#pragma unroll
                for (int ntp = 0; ntp < 4; ntp++) {
                    uint32_t b0, b1, b2, b3;
                    ldsm_x4(b0, b1, b2, b3, b_addr[buf][ntp] + (uint32_t)(ks * 32));
                    uint32_t be[2] = { b0, b1 };
                    uint32_t bo[2] = { b2, b3 };
#pragma unroll
                    for (int mt = 0; mt < 4; mt++) {
                        mma_fp16(acc[mt][ntp * 2 + 0], afr[mt], be);
                        mma_fp16(acc[mt][ntp * 2 + 1], afr[mt], bo);
                    }
                }
            }
            __syncthreads();                       // all reads done before refill
            if (s < 6) issueW(nc, s + 2, s & 1);
        }

        // prefetch chunk-1 W while we run the chunk-0 epilogue
        if (nc == 0) { issueW(1, 0, 0); issueW(1, 1, 1); }

        // fused epilogue: + ha + b_ep, tanh, * w_v, accumulate into spart
#pragma unroll
        for (int mt = 0; mt < 4; mt++) {
#pragma unroll
            for (int qr = 0; qr < 2; qr++) {
                const int rowl = wm * 64 + mt * 16 + qr * 8 + g;
                const int brow = (m0 + rowl) & 255;
                const float* harow = ha + (size_t)brow * 512;
                float acc_s = 0.f;
#pragma unroll
                for (int nt = 0; nt < 8; nt++) {
                    const int col0 = nc * 256 + wn * 64 + nt * 8 + 2 * t4;
                    float2 hv = *reinterpret_cast<const float2*>(harow + col0);
                    float v0 = acc[mt][nt][qr * 2 + 0] + hv.x + bep_sm[col0];
                    float v1 = acc[mt][nt][qr * 2 + 1] + hv.y + bep_sm[col0 + 1];
                    acc_s += wv_sm[col0] * tanh_fast(v0);
                    acc_s += wv_sm[col0 + 1] * tanh_fast(v1);
                }
                spart[mt * 2 + qr] += acc_s;
            }
        }
    }

    // deterministic reduction: quad (t4) via shfl, then across the 4 N-warps via smem
#pragma unroll
    for (int i = 0; i < 8; i++) {
        spart[i] += __shfl_xor_sync(0xffffffffu, spart[i], 1);
        spart[i] += __shfl_xor_sync(0xffffffffu, spart[i], 2);
    }
    __syncthreads();
    if (t4 == 0) {
#pragma unroll
        for (int i = 0; i < 8; i++) {
            int rowl = wm * 64 + (i >> 1) * 16 + (i & 1) * 8 + g;
            stage_sm[wn * 128 + rowl] = spart[i];
        }
    }
    __syncthreads();
    if (tid < 128) {
        float s = stage_sm[tid] + stage_sm[128 + tid] + stage_sm[256 + tid] +
                  stage_sm[384 + tid] + bv[0];
        int m = m0 + tid;
        scores[(size_t)(m & 255) * TT + (m >> 8)] = s;
    }
}

// ---------------- W_ep transpose+convert: Wt[n][k] = fp16(W[k][n]) ----------------
__global__ void transpose_h(const float* __restrict__ src, __half* __restrict__ dst) {
    __shared__ float t[32][33];
    const int tx = threadIdx.x, ty = threadIdx.y;
    const int kx = blockIdx.y * 32;
    const int nx = blockIdx.x * 32;
#pragma unroll
    for (int i = ty; i < 32; i += 8)
        t[i][tx] = src[(size_t)(kx + i) * 512 + nx + tx];
    __syncthreads();
#pragma unroll
    for (int i = ty; i < 32; i += 8)
        dst[(size_t)(nx + i) * 512 + kx + tx] = __float2half_rn(t[tx][i]);
}

// ---------------- generic tiled fp32 SGEMM + bias ----------------
__global__ void __launch_bounds__(256)
sgemm_bias(const float* __restrict__ A, const float* __restrict__ B,
           const float* __restrict__ bias, float* __restrict__ C,
           int N, int K, int ldc) {
    __shared__ float As[16][68];
    __shared__ float Bs[16][68];
    const int tid = threadIdx.x;
    const int tx = tid & 15, ty = tid >> 4;
    const int m0 = blockIdx.y * 64, n0 = blockIdx.x * 64;
    float acc[4][4] = {};

    for (int k0 = 0; k0 < K; k0 += 16) {
#pragma unroll
        for (int i = 0; i < 4; i++) {
            int idx = tid + i * 256;
            int r = idx >> 4, kc = idx & 15;
            float v = 0.f;
            if (k0 + kc < K) v = A[(size_t)(m0 + r) * K + k0 + kc];
            As[kc][r] = v;
        }
#pragma unroll
        for (int i = 0; i < 4; i++) {
            int idx = tid + i * 256;
            int kr = idx >> 6, c = idx & 63;
            float v = 0.f;
            if (k0 + kr < K && n0 + c < N) v = B[(size_t)(k0 + kr) * N + n0 + c];
            Bs[kr][c] = v;
        }
        __syncthreads();
#pragma unroll
        for (int kc = 0; kc < 16; kc++) {
            float a[4], bb[4];
#pragma unroll
            for (int i = 0; i < 4; i++) a[i] = As[kc][ty * 4 + i];
#pragma unroll
            for (int j = 0; j < 4; j++) bb[j] = Bs[kc][tx * 4 + j];
#pragma unroll
            for (int i = 0; i < 4; i++)
#pragma unroll
                for (int j = 0; j < 4; j++) acc[i][j] += a[i] * bb[j];
        }
        __syncthreads();
    }
#pragma unroll
    for (int i = 0; i < 4; i++) {
#pragma unroll
        for (int j = 0; j < 4; j++) {
            int col = n0 + tx * 4 + j;
            if (col < N)
                C[(size_t)(m0 + ty * 4 + i) * ldc + col] = acc[i][j] + bias[col];
        }
    }
}

// ---------------- fused dual SGEMM: ha = hidden@W_hp+b_hp (N=512) and
//                                    gh = hidden@W_hh+b_hh (N=1536); A shared, K=512
__global__ void __launch_bounds__(256)
dual_sgemm(const float* __restrict__ A,
           const float* __restrict__ B1, const float* __restrict__ bias1,
           float* __restrict__ C1,
           const float* __restrict__ B2, const float* __restrict__ bias2,
           float* __restrict__ C2) {
    __shared__ float As[16][68];
    __shared__ float Bs[16][68];
    const int tid = threadIdx.x;
    const int tx = tid & 15, ty = tid >> 4;
    const bool first = blockIdx.x < 8;
    const float* B   = first ? B1 : B2;
    const float* bias = first ? bias1 : bias2;
    float* C = first ? C1 : C2;
    const int N   = first ? 512 : 1536;
    const int n0  = (first ? blockIdx.x : (blockIdx.x - 8)) * 64;
    const int m0  = blockIdx.y * 64;
    float acc[4][4] = {};

    for (int k0 = 0; k0 < 512; k0 += 16) {
#pragma unroll
        for (int i = 0; i < 4; i++) {
            int idx = tid + i * 256;
            int r = idx >> 4, kc = idx & 15;
            As[kc][r] = A[(size_t)(m0 + r) * 512 + k0 + kc];
        }
#pragma unroll
        for (int i = 0; i < 4; i++) {
            int idx = tid + i * 256;
            int kr = idx >> 6, c = idx & 63;
            Bs[kr][c] = B[(size_t)(k0 + kr) * N + n0 + c];
        }
        __syncthreads();
#pragma unroll
        for (int kc = 0; kc < 16; kc++) {
            float a[4], bb[4];
#pragma unroll
            for (int i = 0; i < 4; i++) a[i] = As[kc][ty * 4 + i];
#pragma unroll
            for (int j = 0; j < 4; j++) bb[j] = Bs[kc][tx * 4 + j];
#pragma unroll
            for (int i = 0; i < 4; i++)
#pragma unroll
                for (int j = 0; j < 4; j++) acc[i][j] += a[i] * bb[j];
        }
        __syncthreads();
    }
#pragma unroll
    for (int i = 0; i < 4; i++)
#pragma unroll
        for (int j = 0; j < 4; j++) {
            int col = n0 + tx * 4 + j;
            C[(size_t)(m0 + ty * 4 + i) * N + col] = acc[i][j] + bias[col];
        }
}

// ---------------- softmax over T=600 -> attn in d_out ----------------
__global__ void softmax_attn(const float* __restrict__ scores, float* __restrict__ attn) {
    __shared__ float red[256];
    const int b = blockIdx.x, tid = threadIdx.x;
    const float* s = scores + b * TT;
    float* o = attn + b * TT;

    float m = -1e30f;
    for (int t = tid; t < TT; t += 256) m = fmaxf(m, s[t]);
    red[tid] = m;
    __syncthreads();
    for (int st = 128; st > 0; st >>= 1) {
        if (tid < st) red[tid] = fmaxf(red[tid], red[tid + st]);
        __syncthreads();
    }
    m = red[0];
    __syncthreads();

    float sum = 0.f;
    for (int t = tid; t < TT; t += 256) {
        float e = expf(s[t] - m);
        o[t] = e;
        sum += e;
    }
    red[tid] = sum;
    __syncthreads();
    for (int st = 128; st > 0; st >>= 1) {
        if (tid < st) red[tid] += red[tid + st];
        __syncthreads();
    }
    float inv = 1.f / red[0];
    for (int t = tid; t < TT; t += 256) o[t] *= inv;
}

// ---------------- context split-T partials: part[ts][b][h] = sum_{t in slice} ----
__global__ void __launch_bounds__(128)
ctx_part(const float* __restrict__ enc, const float* __restrict__ attn,
         float* __restrict__ part) {
    __shared__ float a_sm[150];
    const int ts = blockIdx.x;       // 0..3
    const int b  = blockIdx.y;       // 0..255
    const int tid = threadIdx.x;     // 0..127, handles float4 of h
    const int t0 = ts * 150;
    for (int t = tid; t < 150; t += 128) a_sm[t] = attn[b * TT + t0 + t];
    __syncthreads();
    const float* base = enc + (size_t)(t0)*131072 + (size_t)b * 512 + tid * 4;
    float4 acc = make_float4(0.f, 0.f, 0.f, 0.f);
#pragma unroll 5
    for (int i = 0; i < 150; i++) {
        float a = a_sm[i];
        float4 v = *reinterpret_cast<const float4*>(base + (size_t)i * 131072);
        acc.x += a * v.x; acc.y += a * v.y; acc.z += a * v.z; acc.w += a * v.w;
    }
    *reinterpret_cast<float4*>(part + ((size_t)ts * 256 + b) * 512 + tid * 4) = acc;
}

__global__ void ctx_reduce(const float* __restrict__ part, float* __restrict__ ctx) {
    const int idx = blockIdx.x * 256 + threadIdx.x;   // < 131072
    float s = (part[idx] + part[131072 + idx]) +
              (part[262144 + idx] + part[393216 + idx]);
    ctx[idx] = s;
}

// ---------------- argmax over vocab + embedding gather ----------------
__global__ void argmax_embed(const float* __restrict__ in_char, const float* __restrict__ emb,
                             float* __restrict__ indec) {
    const int b = threadIdx.x;
    const float* row = in_char + b * NVOCAB;
    float m = row[0];
    int idx = 0;
    for (int v = 1; v < NVOCAB; v++) {
        float x = row[v];
        if (x > m) { m = x; idx = v; }
    }
    const float* e = emb + idx * 50;
    float* o = indec + b * 300;
    for (int j = 0; j < 50; j++) o[j] = e[j];
}

// ---------------- GRU cell elementwise ----------------
__global__ void gru_kernel(const float* __restrict__ gi, const float* __restrict__ gh,
                           const float* __restrict__ h, float* __restrict__ newh) {
    const int idx = blockIdx.x * 256 + threadIdx.x;
    const int b = idx >> 9, n = idx & 511;
    const float* gib = gi + b * 1536;
    const float* ghb = gh + b * 1536;
    float ir = gib[n], iz = gib[512 + n], in_ = gib[1024 + n];
    float hr = ghb[n], hz = ghb[512 + n], hn = ghb[1024 + n];
    float r = 1.f / (1.f + expf(-(ir + hr)));
    float z = 1.f / (1.f + expf(-(iz + hz)));
    float nn = tanhf(in_ + r * hn);
    newh[idx] = (1.f - z) * nn + z * h[idx];
}

// ---------------- fused output head: softmax(new_h @ W_out + b_out) ----------------
__global__ void __launch_bounds__(256)
out_head(const float* __restrict__ newh, const float* __restrict__ Wout,
         const float* __restrict__ bout, float* __restrict__ out) {
    __shared__ float h_sm[512];
    __shared__ float lg[96];
    __shared__ float red[256];
    const int b = blockIdx.x, tid = threadIdx.x;
    const int lane = tid & 31, wp = tid >> 5;     // 8 warps
    for (int i = tid; i < 512; i += 256) h_sm[i] = newh[(size_t)b * 512 + i];
    __syncthreads();

    for (int c = wp; c < NVOCAB; c += 8) {
        float s = 0.f;
        for (int k = lane; k < 512; k += 32)
            s += h_sm[k] * Wout[(size_t)k * NVOCAB + c];
#pragma unroll
        for (int d = 16; d > 0; d >>= 1) s += __shfl_xor_sync(0xffffffffu, s, d);
        if (lane == 0) lg[c] = s + bout[c];
    }
    __syncthreads();

    float v = (tid < NVOCAB) ? lg[tid] : -1e30f;
    red[tid] = v;
    __syncthreads();
    for (int st = 128; st > 0; st >>= 1) {
        if (tid < st) red[tid] = fmaxf(red[tid], red[tid + st]);
        __syncthreads();
    }
    float m = red[0];
    __syncthreads();
    float e = (tid < NVOCAB) ? expf(v - m) : 0.f;
    red[tid] = e;
    __syncthreads();
    for (int st = 128; st > 0; st >>= 1) {
        if (tid < st) red[tid] += red[tid + st];
        __syncthreads();
    }
    if (tid < NVOCAB) out[(size_t)b * NVOCAB + tid] = e / red[0];
}

// ---------------- launch ----------------
extern "C" void kernel_launch(void* const* d_in, const int* in_sizes, int n_in,
                              void* d_out, int out_size) {
    const float* in_char = (const float*)d_in[0];
    const float* hidden  = (const float*)d_in[1];
    const float* enc     = (const float*)d_in[2];
    const float* W_hp = (const float*)d_in[3];
    const float* b_hp = (const float*)d_in[4];
    const float* W_ep = (const float*)d_in[5];
    const float* b_ep = (const float*)d_in[6];
    const float* w_v  = (const float*)d_in[7];
    const float* b_v  = (const float*)d_in[8];
    const float* W_cs = (const float*)d_in[9];
    const float* b_cs = (const float*)d_in[10];
    const float* emb  = (const float*)d_in[11];
    const float* W_ih = (const float*)d_in[12];
    const float* b_ih = (const float*)d_in[13];
    const float* W_hh = (const float*)d_in[14];
    const float* b_hh = (const float*)d_in[15];
    const float* W_out = (const float*)d_in[16];
    const float* b_out = (const float*)d_in[17];

    float* out = (float*)d_out;
    float* out_prob = out;
    float* out_newh = out + OFF_NEWH;
    float* out_attn = out + OFF_ATTN;

    float *ha, *scores, *ctx, *ctxp, *indec, *gi, *gh;
    __half* Wt;
    cudaGetSymbolAddress((void**)&ha, g_ha);
    cudaGetSymbolAddress((void**)&scores, g_scores);
    cudaGetSymbolAddress((void**)&ctx, g_ctx);
    cudaGetSymbolAddress((void**)&ctxp, g_ctxp);
    cudaGetSymbolAddress((void**)&indec, g_indec);
    cudaGetSymbolAddress((void**)&gi, g_gi);
    cudaGetSymbolAddress((void**)&gh, g_gh);
    cudaGetSymbolAddress((void**)&Wt, g_Wt);

    cudaFuncSetAttribute(scores_fp16, cudaFuncAttributeMaxDynamicSharedMemorySize,
                         DYN_SMEM_SCORES);

    // 0) transpose + fp16-convert W_ep -> Wt[n][k]
    transpose_h<<<dim3(16, 16), dim3(32, 8)>>>(W_ep, Wt);

    // 1) ha = hidden@W_hp+b_hp  AND  gh = hidden@W_hh+b_hh  (one fused launch)
    dual_sgemm<<<dim3(32, 4), 256>>>(hidden, W_hp, b_hp, ha, W_hh, b_hh, gh);

    // 2) fused scores: fp16 mma GEMM (ldmatrix) + tanh + w_v reduce
    scores_fp16<<<1200, 256, DYN_SMEM_SCORES>>>(enc, Wt, b_ep, ha, w_v, b_v, scores);

    // 3) attn = softmax(scores) -> d_out
    softmax_attn<<<256, 256>>>(scores, out_attn);

    // 4) context = einsum('bth,bt->bh')  (split-T two-phase, float4)
    ctx_part<<<dim3(4, 256), 128>>>(enc, out_attn, ctxp);
    ctx_reduce<<<512, 256>>>(ctxp, ctx);

    // 5) argmax + embedding into in_dec[:, :50]
    argmax_embed<<<1, 256>>>(in_char, emb, indec);

    // 6) in_dec[:, 50:300] = context @ W_cs + b_cs
    sgemm_bias<<<dim3(4, 4), 256>>>(ctx, W_cs, b_cs, indec + 50, 250, 512, 300);

    // 7) gi = in_dec @ W_ih + b_ih
    sgemm_bias<<<dim3(24, 4), 256>>>(indec, W_ih, b_ih, gi, 1536, 300, 1536);

    // 8) GRU -> new_h in d_out
    gru_kernel<<<512, 256>>>(gi, gh, hidden, out_newh);

    // 9) output = softmax(new_h @ W_out + b_out) -> d_out (fused)
    out_head<<<256, 256>>>(out_newh, W_out, b_out, out_prob);
}